// round 15
// baseline (speedup 1.0000x reference)
#include <cuda_runtime.h>
#include <cuda_fp16.h>
#include <stdint.h>

// PolylineEncoder on fp16 HMMA (mma.sync.f32.f16.f16.f32).
// R15: R13 math/layout verbatim (L1 3-term, single fp16 h plane, L2 2-term),
// batched 2 tiles per loop iteration: barriers 3/tile -> 1.5/tile, phases 2x
// longer (latency amortized), final write uses all 256 threads.
// rel_err must equal R13's 1.190137e-4 exactly (bit-identical math = canary).

#define NEG_INF_F (-1e9f)
#define NT 256
#define TILE_PTS 64

__device__ __align__(16) uint4 g_bfrag [8 * 16 * 32];   // W2 hi/lo frags, 64 KB
__device__ __align__(16) uint4 g_w1frag[16 * 32];       // W1 hi/lo frags, 8 KB

// smem byte offsets
#define SM_STG   0          // 2 bufs x 2 tiles x (2304 x + 256 mask) = 10240
#define PAIR_STRIDE 5120    // per buffer (2 tiles)
#define TILE_STRIDE 2560    // per tile within buffer
#define SM_FLG   10240      // 4 ballots (warps 0,1 -> tile A; 2,3 -> tile B)
#define SM_RED   10304      // 2 tiles x 256 floats = 2048
#define SM_HH    12352      // 2 x 64*64*4 = 32768 (two fp16 h planes)
#define SM_BYTES 45120

// h-plane word index (row p 0..63, word w 0..63), 4-word rotation: 16B blocks
// contiguous (ldmatrix-compatible); conflict-free for epi-1 STS.32 and
// ldmatrix read phases.
__device__ __forceinline__ uint32_t hword(int p, int w) {
    return (uint32_t)(p * 64 + ((w + 4 * (p & 7)) & 63));
}

__device__ __forceinline__ void ldm4(uint32_t r[4], uint32_t addr) {
    asm volatile("ldmatrix.sync.aligned.m8n8.x4.shared.b16 {%0,%1,%2,%3}, [%4];"
                 : "=r"(r[0]), "=r"(r[1]), "=r"(r[2]), "=r"(r[3]) : "r"(addr));
}

__device__ __forceinline__ void mma16816(float acc[4], const uint32_t a[4],
                                         uint32_t b0, uint32_t b1) {
    asm volatile("mma.sync.aligned.m16n8k16.row.col.f32.f16.f16.f32 "
                 "{%0,%1,%2,%3}, {%4,%5,%6,%7}, {%8,%9}, {%0,%1,%2,%3};"
                 : "+f"(acc[0]), "+f"(acc[1]), "+f"(acc[2]), "+f"(acc[3])
                 : "r"(a[0]), "r"(a[1]), "r"(a[2]), "r"(a[3]), "r"(b0), "r"(b1));
}

__device__ __forceinline__ uint32_t hpack(float a, float b) {
    const __half2 h = __floats2half2_rn(a, b);
    return *(const uint32_t*)&h;
}

__device__ __forceinline__ uint32_t hsplit(float v0, float v1, uint32_t& lo) {
    const __half h0 = __float2half_rn(v0), h1 = __float2half_rn(v1);
    lo = hpack(v0 - __half2float(h0), v1 - __half2float(h1));
    const __half2 hh = __halves2half2(h0, h1);
    return *(const uint32_t*)&hh;
}

__device__ __forceinline__ uint32_t wpair(const float* W, int k, int n,
                                          uint32_t& lo, int kmax) {
    const float v0 = (k < kmax)     ? W[k * 128 + n]       : 0.0f;
    const float v1 = (k + 1 < kmax) ? W[(k + 1) * 128 + n] : 0.0f;
    return hsplit(v0, v1, lo);
}

__device__ __forceinline__ void cp16(uint32_t dst, const void* src) {
    asm volatile("cp.async.cg.shared.global [%0], [%1], 16;" :: "r"(dst), "l"(src));
}
#define CP_COMMIT() asm volatile("cp.async.commit_group;" ::: "memory")
#define CP_WAIT1()  asm volatile("cp.async.wait_group 1;" ::: "memory")

// ---- prep: W2 and W1 -> mma B fragments (col-major), fp16 hi+lo ----
__global__ void prep_kernel(const float* __restrict__ W1, const float* __restrict__ W2) {
    const int idx = blockIdx.x * blockDim.x + threadIdx.x;
    if (idx < 8 * 16 * 32) {
        const int lane = idx & 31, nf = (idx >> 5) & 15, s = idx >> 9;
        const int k0 = s * 16 + 2 * (lane & 3);
        const int n  = nf * 8 + (lane >> 2);
        uint32_t l0, l1;
        const uint32_t h0 = wpair(W2, k0,     n, l0, 128);
        const uint32_t h1 = wpair(W2, k0 + 8, n, l1, 128);
        g_bfrag[idx] = make_uint4(h0, h1, l0, l1);
    }
    if (idx < 16 * 32) {
        const int lane = idx & 31, nf = idx >> 5;
        const int k0 = 2 * (lane & 3);
        const int n  = nf * 8 + (lane >> 2);
        uint32_t l0, l1;
        const uint32_t h0 = wpair(W1, k0,     n, l0, 9);
        const uint32_t h1 = wpair(W1, k0 + 8, n, l1, 9);
        g_w1frag[idx] = make_uint4(h0, h1, l0, l1);
    }
}

extern __shared__ unsigned char smB[];

// stage a PAIR of tiles (tile0, tile0+1): 320 cp16 ops over 256 threads
__device__ __forceinline__ void stage_pair(uint32_t sb, int buf,
                                           const float* poly, const int* mask,
                                           int tile0, int tid) {
    const uint32_t dstA = sb + SM_STG + (uint32_t)buf * PAIR_STRIDE;
    const uint32_t dstB = dstA + TILE_STRIDE;
    const char* pA = (const char*)poly + (size_t)tile0 * 2304;
    const char* pB = pA + 2304;
    const char* mA = (const char*)mask + (size_t)tile0 * 256;
    const char* mB = mA + 256;
    if (tid < 144)      cp16(dstA + tid * 16, pA + tid * 16);
    else if (tid < 160) cp16(dstA + 2304 + (tid - 144) * 16, mA + (tid - 144) * 16);
    else                cp16(dstB + (tid - 160) * 16, pB + (tid - 160) * 16);   // B poly 0..95
    if (tid < 48)       cp16(dstB + (96 + tid) * 16, pB + (96 + tid) * 16);     // B poly 96..143
    else if (tid < 64)  cp16(dstB + 2304 + (tid - 48) * 16, mB + (tid - 48) * 16);
}

__global__ void __launch_bounds__(NT, 3)
poly_mma_kernel(const float* __restrict__ poly, const int* __restrict__ mask,
                const float* __restrict__ b1g, const float* __restrict__ b2g,
                float* __restrict__ out, int ntiles)
{
    const int tid = threadIdx.x, wid = tid >> 5, lane = tid & 31;
    uint32_t* flgs = (uint32_t*)(smB + SM_FLG);

    uint32_t sb;
    asm("{ .reg .u64 t; cvta.to.shared.u64 t, %1; cvt.u32.u64 %0, t; }"
        : "=r"(sb) : "l"(smB));

    const int lr = lane >> 2, lc = lane & 3;    // fragment lane coords
    const int mq = wid & 1, nq = wid >> 1;      // warp = (M-quad, N-quarter)
    const int mbase = 32 * mq;

    // per-thread b1 pairs
    float b1r[8];
    #pragma unroll
    for (int nf = 0; nf < 4; ++nf) {
        b1r[2 * nf]     = b1g[nq * 32 + nf * 8 + 2 * lc];
        b1r[2 * nf + 1] = b1g[nq * 32 + nf * 8 + 2 * lc + 1];
    }

    // ldmatrix lane-address components
    const int lsub = lane >> 3;
    const int lrow = (lsub & 1) * 8 + (lane & 7);
    const int lkb  = (lsub >> 1) * 4;

    const int npairs = ntiles >> 1;

    // prologue: prefetch first pair into buf 0
    int buf = 0;
    if (blockIdx.x < npairs) stage_pair(sb, 0, poly, mask, 2 * blockIdx.x, tid);
    CP_COMMIT();

    for (int p = blockIdx.x; p < npairs; p += gridDim.x) {
        const int pn = p + gridDim.x;
        stage_pair(sb, buf ^ 1, poly, mask, 2 * ((pn < npairs) ? pn : p), tid);
        CP_COMMIT();
        CP_WAIT1();
        __syncthreads();       // bar #1

        const uint32_t stg = SM_STG + (uint32_t)buf * PAIR_STRIDE;

        // any-valid ballots: warps 0,1 -> tile A points; warps 2,3 -> tile B
        if (tid < 128) {
            const int half = tid >> 6, pt = tid & 63;
            const int* mk = (const int*)(smB + stg + half * TILE_STRIDE + 2304);
            const uint32_t bal = __ballot_sync(0xffffffffu, mk[pt] != 0);
            if (lane == 0) flgs[wid] = bal;
        }

        // ---- MMA1 + epilogue-1 for both tiles ----
        #pragma unroll 1
        for (int half = 0; half < 2; ++half) {
            const float* xs = (const float*)(smB + stg + half * TILE_STRIDE);
            const uint32_t hh = SM_HH + (uint32_t)half * 16384;

            float acc[2][4][4];
            uint32_t xah[2][4], xal[2][4];
            #pragma unroll
            for (int mi = 0; mi < 2; ++mi) {
                const int rA = mbase + 16 * mi + lr, rB = rA + 8;
                xah[mi][0] = hsplit(xs[rA * 9 + 2 * lc], xs[rA * 9 + 2 * lc + 1], xal[mi][0]);
                xah[mi][1] = hsplit(xs[rB * 9 + 2 * lc], xs[rB * 9 + 2 * lc + 1], xal[mi][1]);
                if (lc == 0) {
                    xah[mi][2] = hsplit(xs[rA * 9 + 8], 0.0f, xal[mi][2]);
                    xah[mi][3] = hsplit(xs[rB * 9 + 8], 0.0f, xal[mi][3]);
                } else {
                    xah[mi][2] = 0; xah[mi][3] = 0; xal[mi][2] = 0; xal[mi][3] = 0;
                }
            }
            #pragma unroll
            for (int mi = 0; mi < 2; ++mi)
                #pragma unroll
                for (int nf = 0; nf < 4; ++nf)
                    #pragma unroll
                    for (int e = 0; e < 4; ++e) acc[mi][nf][e] = 0.0f;
            #pragma unroll
            for (int nf = 0; nf < 4; ++nf) {
                const uint4 B = __ldg(&g_w1frag[(nq * 4 + nf) * 32 + lane]);
                #pragma unroll
                for (int mi = 0; mi < 2; ++mi) {
                    mma16816(acc[mi][nf], xah[mi], B.x, B.y);   // xh * W1h
                    mma16816(acc[mi][nf], xah[mi], B.z, B.w);   // xh * W1l
                    mma16816(acc[mi][nf], xal[mi], B.x, B.y);   // xl * W1h
                }
            }
            // epilogue-1: +b1, relu, round to fp16 -> this tile's h plane
            #pragma unroll
            for (int nf = 0; nf < 4; ++nf) {
                const int w = nq * 16 + nf * 4 + lc;
                #pragma unroll
                for (int mi = 0; mi < 2; ++mi) {
                    const int r = mbase + 16 * mi + lr;
                    const float e0 = fmaxf(acc[mi][nf][0] + b1r[2 * nf],     0.0f);
                    const float e1 = fmaxf(acc[mi][nf][1] + b1r[2 * nf + 1], 0.0f);
                    const float e2 = fmaxf(acc[mi][nf][2] + b1r[2 * nf],     0.0f);
                    const float e3 = fmaxf(acc[mi][nf][3] + b1r[2 * nf + 1], 0.0f);
                    *(uint32_t*)(smB + hh + 4 * hword(r, w))     = hpack(e0, e1);
                    *(uint32_t*)(smB + hh + 4 * hword(r + 8, w)) = hpack(e2, e3);
                }
            }
        }
        __syncthreads();       // bar #2

        // ---- MMA2 + epilogue-2 for both tiles ----
        #pragma unroll 1
        for (int half = 0; half < 2; ++half) {
            const int* msks = (const int*)(smB + stg + half * TILE_STRIDE + 2304);
            const uint32_t hh = SM_HH + (uint32_t)half * 16384;
            float* red = (float*)(smB + SM_RED) + half * 256;

            float acc[2][4][4];
            #pragma unroll
            for (int mi = 0; mi < 2; ++mi)
                #pragma unroll
                for (int nf = 0; nf < 4; ++nf)
                    #pragma unroll
                    for (int e = 0; e < 4; ++e) acc[mi][nf][e] = 0.0f;

            #pragma unroll 1
            for (int s = 0; s < 8; ++s) {
                uint32_t ah[2][4];
                const int w0 = 8 * s + lkb;
                #pragma unroll
                for (int mi = 0; mi < 2; ++mi)
                    ldm4(ah[mi], sb + hh + 4 * hword(mbase + 16 * mi + lrow, w0));
                #pragma unroll
                for (int nf = 0; nf < 4; ++nf) {
                    const uint4 B = __ldg(&g_bfrag[(s * 16 + nq * 4 + nf) * 32 + lane]);
                    #pragma unroll
                    for (int mi = 0; mi < 2; ++mi) {
                        mma16816(acc[mi][nf], ah[mi], B.x, B.y);   // h * W2h
                        mma16816(acc[mi][nf], ah[mi], B.z, B.w);   // h * W2l
                    }
                }
            }

            // epilogue-2: masked max over the warp's 32 points
            const int m00 = msks[mbase + lr] != 0,      m01 = msks[mbase + lr + 8] != 0;
            const int m10 = msks[mbase + 16 + lr] != 0, m11 = msks[mbase + 24 + lr] != 0;
            #pragma unroll
            for (int nf = 0; nf < 4; ++nf) {
                float e0 = NEG_INF_F, e1 = NEG_INF_F;
                if (m00) { e0 = fmaxf(e0, acc[0][nf][0]); e1 = fmaxf(e1, acc[0][nf][1]); }
                if (m01) { e0 = fmaxf(e0, acc[0][nf][2]); e1 = fmaxf(e1, acc[0][nf][3]); }
                if (m10) { e0 = fmaxf(e0, acc[1][nf][0]); e1 = fmaxf(e1, acc[1][nf][1]); }
                if (m11) { e0 = fmaxf(e0, acc[1][nf][2]); e1 = fmaxf(e1, acc[1][nf][3]); }
                #pragma unroll
                for (int off = 4; off < 32; off <<= 1) {
                    e0 = fmaxf(e0, __shfl_xor_sync(0xffffffffu, e0, off));
                    e1 = fmaxf(e1, __shfl_xor_sync(0xffffffffu, e1, off));
                }
                if (lane < 4) {
                    const int n = nq * 32 + nf * 8 + 2 * lane;
                    red[mq * 128 + n]     = e0;
                    red[mq * 128 + n + 1] = e1;
                }
            }
        }
        __syncthreads();       // bar #3

        // ---- final: all 256 threads; tid<128 -> tile A, else tile B ----
        {
            const int half = tid >> 7, d = tid & 127;
            const float* red = (const float*)(smB + SM_RED) + half * 256;
            const float v = fmaxf(red[d], red[128 + d]);
            const uint32_t av = flgs[2 * half] | flgs[2 * half + 1];
            out[(size_t)(2 * p + half) * 128 + d] = av ? v + __ldg(&b2g[d]) : 0.0f;
        }

        buf ^= 1;
    }
}

extern "C" void kernel_launch(void* const* d_in, const int* in_sizes, int n_in,
                              void* d_out, int out_size)
{
    const float* poly = (const float*)d_in[0];
    const int*   mask = (const int*)  d_in[1];
    const float* W1   = (const float*)d_in[2];
    const float* b1   = (const float*)d_in[3];
    const float* W2   = (const float*)d_in[4];
    const float* b2   = (const float*)d_in[5];
    float* out = (float*)d_out;

    const int npoints = in_sizes[0] / 9;           // 1,048,576
    const int ntiles  = npoints / TILE_PTS;        // 16384 (even -> 8192 pairs)

    prep_kernel<<<16, 256>>>(W1, W2);

    cudaFuncSetAttribute(poly_mma_kernel,
                         cudaFuncAttributeMaxDynamicSharedMemorySize, SM_BYTES);
    poly_mma_kernel<<<444, NT, SM_BYTES>>>(poly, mask, b1, b2, out, ntiles);
}

// round 16
// speedup vs baseline: 1.6557x; 1.6557x over previous
#include <cuda_runtime.h>
#include <cuda_fp16.h>
#include <stdint.h>

// PolylineEncoder on fp16 HMMA (mma.sync.f32.f16.f16.f32).
// R16: fully single-term fp16 (x,W1,h,W2 all rounded to fp16; fp32 accum).
// 4 x 2^-11 rounding sources -> predicted rel_err ~2.4e-4 (vs 1e-3 budget).
// mma/warp/tile 152 -> 72; hsplit ALU deleted; B fragments uint2 (32 KB
// table). Skeleton identical to R13 (best passing, 213.5us).

#define NEG_INF_F (-1e9f)
#define NT 256
#define TILE_PTS 64

__device__ __align__(16) uint2 g_bfrag [8 * 16 * 32];   // W2 fp16 frags, 32 KB
__device__ __align__(16) uint2 g_w1frag[16 * 32];       // W1 fp16 frags, 4 KB

// smem byte offsets
#define SM_STG   0        // 2 bufs x (2304 x + 256 mask)
#define STG_STRIDE 2560
#define SM_FLG   5120     // 64
#define SM_RED   5184     // 1024
#define SM_HH    6208     // 64*64*4 = 16384 (single fp16 h plane)
#define SM_BYTES 22592

// h-plane word index (row p 0..63, word w 0..63), 4-word rotation: 16B blocks
// contiguous (ldmatrix-compatible); conflict-free for epi-1 STS.32 and
// ldmatrix read phases.
__device__ __forceinline__ uint32_t hword(int p, int w) {
    return (uint32_t)(p * 64 + ((w + 4 * (p & 7)) & 63));
}

__device__ __forceinline__ void ldm4(uint32_t r[4], uint32_t addr) {
    asm volatile("ldmatrix.sync.aligned.m8n8.x4.shared.b16 {%0,%1,%2,%3}, [%4];"
                 : "=r"(r[0]), "=r"(r[1]), "=r"(r[2]), "=r"(r[3]) : "r"(addr));
}

__device__ __forceinline__ void mma16816(float acc[4], const uint32_t a[4],
                                         uint32_t b0, uint32_t b1) {
    asm volatile("mma.sync.aligned.m16n8k16.row.col.f32.f16.f16.f32 "
                 "{%0,%1,%2,%3}, {%4,%5,%6,%7}, {%8,%9}, {%0,%1,%2,%3};"
                 : "+f"(acc[0]), "+f"(acc[1]), "+f"(acc[2]), "+f"(acc[3])
                 : "r"(a[0]), "r"(a[1]), "r"(a[2]), "r"(a[3]), "r"(b0), "r"(b1));
}

__device__ __forceinline__ uint32_t hpack(float a, float b) {
    const __half2 h = __floats2half2_rn(a, b);
    return *(const uint32_t*)&h;
}

__device__ __forceinline__ uint32_t wpairh(const float* W, int k, int n, int kmax) {
    const float v0 = (k < kmax)     ? W[k * 128 + n]       : 0.0f;
    const float v1 = (k + 1 < kmax) ? W[(k + 1) * 128 + n] : 0.0f;
    return hpack(v0, v1);
}

__device__ __forceinline__ void cp16(uint32_t dst, const void* src) {
    asm volatile("cp.async.cg.shared.global [%0], [%1], 16;" :: "r"(dst), "l"(src));
}
#define CP_COMMIT() asm volatile("cp.async.commit_group;" ::: "memory")
#define CP_WAIT1()  asm volatile("cp.async.wait_group 1;" ::: "memory")

// ---- prep: W2 and W1 -> mma B fragments (col-major), fp16 ----
__global__ void prep_kernel(const float* __restrict__ W1, const float* __restrict__ W2) {
    const int idx = blockIdx.x * blockDim.x + threadIdx.x;
    if (idx < 8 * 16 * 32) {
        const int lane = idx & 31, nf = (idx >> 5) & 15, s = idx >> 9;
        const int k0 = s * 16 + 2 * (lane & 3);
        const int n  = nf * 8 + (lane >> 2);
        g_bfrag[idx] = make_uint2(wpairh(W2, k0, n, 128), wpairh(W2, k0 + 8, n, 128));
    }
    if (idx < 16 * 32) {
        const int lane = idx & 31, nf = idx >> 5;
        const int k0 = 2 * (lane & 3);
        const int n  = nf * 8 + (lane >> 2);
        g_w1frag[idx] = make_uint2(wpairh(W1, k0, n, 9), wpairh(W1, k0 + 8, n, 9));
    }
}

extern __shared__ unsigned char smB[];

__device__ __forceinline__ void stage_tile(uint32_t sb, int buf,
                                           const float* poly, const int* mask,
                                           int tile, int tid) {
    const uint32_t dst = sb + SM_STG + (uint32_t)buf * STG_STRIDE;
    if (tid < 144)
        cp16(dst + tid * 16, (const char*)poly + (size_t)tile * 2304 + tid * 16);
    else if (tid < 160)
        cp16(dst + 2304 + (tid - 144) * 16,
             (const char*)mask + (size_t)tile * 256 + (tid - 144) * 16);
}

__global__ void __launch_bounds__(NT, 3)
poly_mma_kernel(const float* __restrict__ poly, const int* __restrict__ mask,
                const float* __restrict__ b1g, const float* __restrict__ b2g,
                float* __restrict__ out, int ntiles)
{
    const int tid = threadIdx.x, wid = tid >> 5, lane = tid & 31;
    uint32_t* flgs = (uint32_t*)(smB + SM_FLG);
    float* red = (float*)(smB + SM_RED);

    uint32_t sb;
    asm("{ .reg .u64 t; cvta.to.shared.u64 t, %1; cvt.u32.u64 %0, t; }"
        : "=r"(sb) : "l"(smB));

    const int lr = lane >> 2, lc = lane & 3;    // fragment lane coords
    const int mq = wid & 1, nq = wid >> 1;      // warp = (M-quad, N-quarter)
    const int mbase = 32 * mq;

    // per-thread b1 pairs
    float b1r[8];
    #pragma unroll
    for (int nf = 0; nf < 4; ++nf) {
        b1r[2 * nf]     = b1g[nq * 32 + nf * 8 + 2 * lc];
        b1r[2 * nf + 1] = b1g[nq * 32 + nf * 8 + 2 * lc + 1];
    }

    // W1 fragments constant across tiles: hold in registers (8B x 4)
    uint2 w1B[4];
    #pragma unroll
    for (int nf = 0; nf < 4; ++nf) w1B[nf] = g_w1frag[(nq * 4 + nf) * 32 + lane];

    // ldmatrix lane-address components
    const int lsub = lane >> 3;
    const int lrow = (lsub & 1) * 8 + (lane & 7);
    const int lkb  = (lsub >> 1) * 4;

    // prologue: prefetch first tile into buf 0
    int buf = 0;
    if (blockIdx.x < ntiles) stage_tile(sb, 0, poly, mask, blockIdx.x, tid);
    CP_COMMIT();

    for (int tile = blockIdx.x; tile < ntiles; tile += gridDim.x) {
        const int tn = tile + gridDim.x;
        stage_tile(sb, buf ^ 1, poly, mask, (tn < ntiles) ? tn : tile, tid);
        CP_COMMIT();
        CP_WAIT1();
        __syncthreads();       // bar #1

        const float* xs = (const float*)(smB + SM_STG + (uint32_t)buf * STG_STRIDE);
        const int* msks = (const int*)(smB + SM_STG + (uint32_t)buf * STG_STRIDE + 2304);

        if (tid < TILE_PTS) {
            const uint32_t bal = __ballot_sync(0xffffffffu, msks[tid] != 0);
            if (lane == 0) flgs[wid] = bal;
        }

        float acc[2][4][4];

        // ---- MMA1: h = x @ W1 (K=16, single-term fp16) ----
        {
            uint32_t xah[2][4];
            #pragma unroll
            for (int mi = 0; mi < 2; ++mi) {
                const int rA = mbase + 16 * mi + lr, rB = rA + 8;
                xah[mi][0] = hpack(xs[rA * 9 + 2 * lc], xs[rA * 9 + 2 * lc + 1]);
                xah[mi][1] = hpack(xs[rB * 9 + 2 * lc], xs[rB * 9 + 2 * lc + 1]);
                if (lc == 0) {
                    xah[mi][2] = hpack(xs[rA * 9 + 8], 0.0f);
                    xah[mi][3] = hpack(xs[rB * 9 + 8], 0.0f);
                } else {
                    xah[mi][2] = 0; xah[mi][3] = 0;
                }
            }
            #pragma unroll
            for (int mi = 0; mi < 2; ++mi)
                #pragma unroll
                for (int nf = 0; nf < 4; ++nf)
                    #pragma unroll
                    for (int e = 0; e < 4; ++e) acc[mi][nf][e] = 0.0f;
            #pragma unroll
            for (int nf = 0; nf < 4; ++nf)
                #pragma unroll
                for (int mi = 0; mi < 2; ++mi)
                    mma16816(acc[mi][nf], xah[mi], w1B[nf].x, w1B[nf].y);

            // epilogue-1: +b1, relu, round to fp16 -> single h plane
            #pragma unroll
            for (int nf = 0; nf < 4; ++nf) {
                const int w = nq * 16 + nf * 4 + lc;
                #pragma unroll
                for (int mi = 0; mi < 2; ++mi) {
                    const int r = mbase + 16 * mi + lr;
                    const float e0 = fmaxf(acc[mi][nf][0] + b1r[2 * nf],     0.0f);
                    const float e1 = fmaxf(acc[mi][nf][1] + b1r[2 * nf + 1], 0.0f);
                    const float e2 = fmaxf(acc[mi][nf][2] + b1r[2 * nf],     0.0f);
                    const float e3 = fmaxf(acc[mi][nf][3] + b1r[2 * nf + 1], 0.0f);
                    *(uint32_t*)(smB + SM_HH + 4 * hword(r, w))     = hpack(e0, e1);
                    *(uint32_t*)(smB + SM_HH + 4 * hword(r + 8, w)) = hpack(e2, e3);
                }
            }
        }
        __syncthreads();       // bar #2

        // ---- MMA2: feat = h @ W2 (K=128, single-term fp16) ----
        #pragma unroll
        for (int mi = 0; mi < 2; ++mi)
            #pragma unroll
            for (int nf = 0; nf < 4; ++nf)
                #pragma unroll
                for (int e = 0; e < 4; ++e) acc[mi][nf][e] = 0.0f;

        #pragma unroll 1
        for (int s = 0; s < 8; ++s) {
            uint32_t ah[2][4];
            const int w0 = 8 * s + lkb;
            #pragma unroll
            for (int mi = 0; mi < 2; ++mi)
                ldm4(ah[mi], sb + SM_HH + 4 * hword(mbase + 16 * mi + lrow, w0));
            #pragma unroll
            for (int nf = 0; nf < 4; ++nf) {
                const uint2 B = __ldg(&g_bfrag[(s * 16 + nq * 4 + nf) * 32 + lane]);
                #pragma unroll
                for (int mi = 0; mi < 2; ++mi)
                    mma16816(acc[mi][nf], ah[mi], B.x, B.y);
            }
        }

        // ---- epilogue-2: masked max over the warp's 32 points ----
        const int m00 = msks[mbase + lr] != 0,      m01 = msks[mbase + lr + 8] != 0;
        const int m10 = msks[mbase + 16 + lr] != 0, m11 = msks[mbase + 24 + lr] != 0;
        #pragma unroll
        for (int nf = 0; nf < 4; ++nf) {
            float e0 = NEG_INF_F, e1 = NEG_INF_F;
            if (m00) { e0 = fmaxf(e0, acc[0][nf][0]); e1 = fmaxf(e1, acc[0][nf][1]); }
            if (m01) { e0 = fmaxf(e0, acc[0][nf][2]); e1 = fmaxf(e1, acc[0][nf][3]); }
            if (m10) { e0 = fmaxf(e0, acc[1][nf][0]); e1 = fmaxf(e1, acc[1][nf][1]); }
            if (m11) { e0 = fmaxf(e0, acc[1][nf][2]); e1 = fmaxf(e1, acc[1][nf][3]); }
            #pragma unroll
            for (int off = 4; off < 32; off <<= 1) {
                e0 = fmaxf(e0, __shfl_xor_sync(0xffffffffu, e0, off));
                e1 = fmaxf(e1, __shfl_xor_sync(0xffffffffu, e1, off));
            }
            if (lane < 4) {
                const int n = nq * 32 + nf * 8 + 2 * lane;
                red[mq * 128 + n]     = e0;
                red[mq * 128 + n + 1] = e1;
            }
        }
        __syncthreads();       // bar #3

        // ---- final: combine 2 M-quads, +b2, any-valid (1 polyline/tile) ----
        if (tid < 128) {
            const float v = fmaxf(red[tid], red[128 + tid]);
            const uint32_t av = flgs[0] | flgs[1];
            out[(size_t)tile * 128 + tid] = av ? v + __ldg(&b2g[tid]) : 0.0f;
        }

        buf ^= 1;
    }
}

extern "C" void kernel_launch(void* const* d_in, const int* in_sizes, int n_in,
                              void* d_out, int out_size)
{
    const float* poly = (const float*)d_in[0];
    const int*   mask = (const int*)  d_in[1];
    const float* W1   = (const float*)d_in[2];
    const float* b1   = (const float*)d_in[3];
    const float* W2   = (const float*)d_in[4];
    const float* b2   = (const float*)d_in[5];
    float* out = (float*)d_out;

    const int npoints = in_sizes[0] / 9;           // 1,048,576
    const int ntiles  = npoints / TILE_PTS;        // 16384

    prep_kernel<<<16, 256>>>(W1, W2);

    cudaFuncSetAttribute(poly_mma_kernel,
                         cudaFuncAttributeMaxDynamicSharedMemorySize, SM_BYTES);
    poly_mma_kernel<<<444, NT, SM_BYTES>>>(poly, mask, b1, b2, out, ntiles);
}

// round 17
// speedup vs baseline: 1.7972x; 1.0855x over previous
#include <cuda_runtime.h>
#include <cuda_fp16.h>
#include <stdint.h>

// PolylineEncoder on fp16 HMMA (mma.sync.f32.f16.f16.f32).
// R17: R16 (single-term fp16, 131.2us) + W2 fragment table staged into SMEM
// once per CTA (LDS 29cyc replaces LDG L1 39cyc on MMA2's critical path;
// frees L1D for cp.async staging). Math identical -> rel_err 2.464694e-4.

#define NEG_INF_F (-1e9f)
#define NT 256
#define TILE_PTS 64

__device__ __align__(16) uint2 g_bfrag [8 * 16 * 32];   // W2 fp16 frags, 32 KB
__device__ __align__(16) uint2 g_w1frag[16 * 32];       // W1 fp16 frags, 4 KB

// smem byte offsets
#define SM_STG   0        // 2 bufs x (2304 x + 256 mask)
#define STG_STRIDE 2560
#define SM_FLG   5120     // 64
#define SM_RED   5184     // 1024
#define SM_HH    6208     // 64*64*4 = 16384 (single fp16 h plane)
#define SM_W2F   22592    // 32768 (W2 fragment table, copied from global once)
#define SM_BYTES 55360

// h-plane word index (row p 0..63, word w 0..63), 4-word rotation: 16B blocks
// contiguous (ldmatrix-compatible); conflict-free for epi-1 STS.32 and
// ldmatrix read phases.
__device__ __forceinline__ uint32_t hword(int p, int w) {
    return (uint32_t)(p * 64 + ((w + 4 * (p & 7)) & 63));
}

__device__ __forceinline__ void ldm4(uint32_t r[4], uint32_t addr) {
    asm volatile("ldmatrix.sync.aligned.m8n8.x4.shared.b16 {%0,%1,%2,%3}, [%4];"
                 : "=r"(r[0]), "=r"(r[1]), "=r"(r[2]), "=r"(r[3]) : "r"(addr));
}

__device__ __forceinline__ void mma16816(float acc[4], const uint32_t a[4],
                                         uint32_t b0, uint32_t b1) {
    asm volatile("mma.sync.aligned.m16n8k16.row.col.f32.f16.f16.f32 "
                 "{%0,%1,%2,%3}, {%4,%5,%6,%7}, {%8,%9}, {%0,%1,%2,%3};"
                 : "+f"(acc[0]), "+f"(acc[1]), "+f"(acc[2]), "+f"(acc[3])
                 : "r"(a[0]), "r"(a[1]), "r"(a[2]), "r"(a[3]), "r"(b0), "r"(b1));
}

__device__ __forceinline__ uint32_t hpack(float a, float b) {
    const __half2 h = __floats2half2_rn(a, b);
    return *(const uint32_t*)&h;
}

__device__ __forceinline__ uint32_t wpairh(const float* W, int k, int n, int kmax) {
    const float v0 = (k < kmax)     ? W[k * 128 + n]       : 0.0f;
    const float v1 = (k + 1 < kmax) ? W[(k + 1) * 128 + n] : 0.0f;
    return hpack(v0, v1);
}

__device__ __forceinline__ void cp16(uint32_t dst, const void* src) {
    asm volatile("cp.async.cg.shared.global [%0], [%1], 16;" :: "r"(dst), "l"(src));
}
#define CP_COMMIT() asm volatile("cp.async.commit_group;" ::: "memory")
#define CP_WAIT1()  asm volatile("cp.async.wait_group 1;" ::: "memory")

// ---- prep: W2 and W1 -> mma B fragments (col-major), fp16 ----
__global__ void prep_kernel(const float* __restrict__ W1, const float* __restrict__ W2) {
    const int idx = blockIdx.x * blockDim.x + threadIdx.x;
    if (idx < 8 * 16 * 32) {
        const int lane = idx & 31, nf = (idx >> 5) & 15, s = idx >> 9;
        const int k0 = s * 16 + 2 * (lane & 3);
        const int n  = nf * 8 + (lane >> 2);
        g_bfrag[idx] = make_uint2(wpairh(W2, k0, n, 128), wpairh(W2, k0 + 8, n, 128));
    }
    if (idx < 16 * 32) {
        const int lane = idx & 31, nf = idx >> 5;
        const int k0 = 2 * (lane & 3);
        const int n  = nf * 8 + (lane >> 2);
        g_w1frag[idx] = make_uint2(wpairh(W1, k0, n, 9), wpairh(W1, k0 + 8, n, 9));
    }
}

extern __shared__ unsigned char smB[];

__device__ __forceinline__ void stage_tile(uint32_t sb, int buf,
                                           const float* poly, const int* mask,
                                           int tile, int tid) {
    const uint32_t dst = sb + SM_STG + (uint32_t)buf * STG_STRIDE;
    if (tid < 144)
        cp16(dst + tid * 16, (const char*)poly + (size_t)tile * 2304 + tid * 16);
    else if (tid < 160)
        cp16(dst + 2304 + (tid - 144) * 16,
             (const char*)mask + (size_t)tile * 256 + (tid - 144) * 16);
}

__global__ void __launch_bounds__(NT, 3)
poly_mma_kernel(const float* __restrict__ poly, const int* __restrict__ mask,
                const float* __restrict__ b1g, const float* __restrict__ b2g,
                float* __restrict__ out, int ntiles)
{
    const int tid = threadIdx.x, wid = tid >> 5, lane = tid & 31;
    uint32_t* flgs = (uint32_t*)(smB + SM_FLG);
    float* red = (float*)(smB + SM_RED);

    uint32_t sb;
    asm("{ .reg .u64 t; cvta.to.shared.u64 t, %1; cvt.u32.u64 %0, t; }"
        : "=r"(sb) : "l"(smB));

    // ---- one-time: copy W2 fragment table into smem (2048 uint4) ----
    {
        const uint4* src = (const uint4*)g_bfrag;
        uint4* dst = (uint4*)(smB + SM_W2F);
        #pragma unroll
        for (int i = 0; i < 8; ++i) dst[i * 256 + tid] = src[i * 256 + tid];
    }

    const int lr = lane >> 2, lc = lane & 3;    // fragment lane coords
    const int mq = wid & 1, nq = wid >> 1;      // warp = (M-quad, N-quarter)
    const int mbase = 32 * mq;

    // per-thread b1 pairs
    float b1r[8];
    #pragma unroll
    for (int nf = 0; nf < 4; ++nf) {
        b1r[2 * nf]     = b1g[nq * 32 + nf * 8 + 2 * lc];
        b1r[2 * nf + 1] = b1g[nq * 32 + nf * 8 + 2 * lc + 1];
    }

    // W1 fragments constant across tiles: hold in registers
    uint2 w1B[4];
    #pragma unroll
    for (int nf = 0; nf < 4; ++nf) w1B[nf] = g_w1frag[(nq * 4 + nf) * 32 + lane];

    // ldmatrix lane-address components
    const int lsub = lane >> 3;
    const int lrow = (lsub & 1) * 8 + (lane & 7);
    const int lkb  = (lsub >> 1) * 4;

    // per-thread base of this warp's B fragments in smem:
    // entry (s*16 + nq*4 + nf)*32 + lane, uint2 (8 B each)
    const uint32_t w2fb = sb + SM_W2F + ((uint32_t)(nq * 4) * 32 + lane) * 8;

    // prologue: prefetch first tile into buf 0
    int buf = 0;
    if (blockIdx.x < ntiles) stage_tile(sb, 0, poly, mask, blockIdx.x, tid);
    CP_COMMIT();

    for (int tile = blockIdx.x; tile < ntiles; tile += gridDim.x) {
        const int tn = tile + gridDim.x;
        stage_tile(sb, buf ^ 1, poly, mask, (tn < ntiles) ? tn : tile, tid);
        CP_COMMIT();
        CP_WAIT1();
        __syncthreads();       // bar #1 (also covers the one-time W2F copy)

        const float* xs = (const float*)(smB + SM_STG + (uint32_t)buf * STG_STRIDE);
        const int* msks = (const int*)(smB + SM_STG + (uint32_t)buf * STG_STRIDE + 2304);

        if (tid < TILE_PTS) {
            const uint32_t bal = __ballot_sync(0xffffffffu, msks[tid] != 0);
            if (lane == 0) flgs[wid] = bal;
        }

        float acc[2][4][4];

        // ---- MMA1: h = x @ W1 (K=16, single-term fp16) ----
        {
            uint32_t xah[2][4];
            #pragma unroll
            for (int mi = 0; mi < 2; ++mi) {
                const int rA = mbase + 16 * mi + lr, rB = rA + 8;
                xah[mi][0] = hpack(xs[rA * 9 + 2 * lc], xs[rA * 9 + 2 * lc + 1]);
                xah[mi][1] = hpack(xs[rB * 9 + 2 * lc], xs[rB * 9 + 2 * lc + 1]);
                if (lc == 0) {
                    xah[mi][2] = hpack(xs[rA * 9 + 8], 0.0f);
                    xah[mi][3] = hpack(xs[rB * 9 + 8], 0.0f);
                } else {
                    xah[mi][2] = 0; xah[mi][3] = 0;
                }
            }
            #pragma unroll
            for (int mi = 0; mi < 2; ++mi)
                #pragma unroll
                for (int nf = 0; nf < 4; ++nf)
                    #pragma unroll
                    for (int e = 0; e < 4; ++e) acc[mi][nf][e] = 0.0f;
            #pragma unroll
            for (int nf = 0; nf < 4; ++nf)
                #pragma unroll
                for (int mi = 0; mi < 2; ++mi)
                    mma16816(acc[mi][nf], xah[mi], w1B[nf].x, w1B[nf].y);

            // epilogue-1: +b1, relu, round to fp16 -> single h plane
            #pragma unroll
            for (int nf = 0; nf < 4; ++nf) {
                const int w = nq * 16 + nf * 4 + lc;
                #pragma unroll
                for (int mi = 0; mi < 2; ++mi) {
                    const int r = mbase + 16 * mi + lr;
                    const float e0 = fmaxf(acc[mi][nf][0] + b1r[2 * nf],     0.0f);
                    const float e1 = fmaxf(acc[mi][nf][1] + b1r[2 * nf + 1], 0.0f);
                    const float e2 = fmaxf(acc[mi][nf][2] + b1r[2 * nf],     0.0f);
                    const float e3 = fmaxf(acc[mi][nf][3] + b1r[2 * nf + 1], 0.0f);
                    *(uint32_t*)(smB + SM_HH + 4 * hword(r, w))     = hpack(e0, e1);
                    *(uint32_t*)(smB + SM_HH + 4 * hword(r + 8, w)) = hpack(e2, e3);
                }
            }
        }
        __syncthreads();       // bar #2

        // ---- MMA2: feat = h @ W2 (K=128, single-term fp16), B from smem ----
        #pragma unroll
        for (int mi = 0; mi < 2; ++mi)
            #pragma unroll
            for (int nf = 0; nf < 4; ++nf)
                #pragma unroll
                for (int e = 0; e < 4; ++e) acc[mi][nf][e] = 0.0f;

        #pragma unroll 1
        for (int s = 0; s < 8; ++s) {
            uint32_t ah[2][4];
            const int w0 = 8 * s + lkb;
            #pragma unroll
            for (int mi = 0; mi < 2; ++mi)
                ldm4(ah[mi], sb + SM_HH + 4 * hword(mbase + 16 * mi + lrow, w0));
            #pragma unroll
            for (int nf = 0; nf < 4; ++nf) {
                const uint2 B = *(const uint2*)(uintptr_t)0;   // placeholder, replaced below
                (void)B;
            }
            // B loads + mma (explicit LDS from smem table)
            #pragma unroll
            for (int nf = 0; nf < 4; ++nf) {
                uint32_t b0, b1;
                asm volatile("ld.shared.v2.u32 {%0, %1}, [%2];"
                             : "=r"(b0), "=r"(b1)
                             : "r"(w2fb + (uint32_t)(s * 16 + nf) * 32 * 8));
                #pragma unroll
                for (int mi = 0; mi < 2; ++mi)
                    mma16816(acc[mi][nf], ah[mi], b0, b1);
            }
        }

        // ---- epilogue-2: masked max over the warp's 32 points ----
        const int m00 = msks[mbase + lr] != 0,      m01 = msks[mbase + lr + 8] != 0;
        const int m10 = msks[mbase + 16 + lr] != 0, m11 = msks[mbase + 24 + lr] != 0;
        #pragma unroll
        for (int nf = 0; nf < 4; ++nf) {
            float e0 = NEG_INF_F, e1 = NEG_INF_F;
            if (m00) { e0 = fmaxf(e0, acc[0][nf][0]); e1 = fmaxf(e1, acc[0][nf][1]); }
            if (m01) { e0 = fmaxf(e0, acc[0][nf][2]); e1 = fmaxf(e1, acc[0][nf][3]); }
            if (m10) { e0 = fmaxf(e0, acc[1][nf][0]); e1 = fmaxf(e1, acc[1][nf][1]); }
            if (m11) { e0 = fmaxf(e0, acc[1][nf][2]); e1 = fmaxf(e1, acc[1][nf][3]); }
            #pragma unroll
            for (int off = 4; off < 32; off <<= 1) {
                e0 = fmaxf(e0, __shfl_xor_sync(0xffffffffu, e0, off));
                e1 = fmaxf(e1, __shfl_xor_sync(0xffffffffu, e1, off));
            }
            if (lane < 4) {
                const int n = nq * 32 + nf * 8 + 2 * lane;
                red[mq * 128 + n]     = e0;
                red[mq * 128 + n + 1] = e1;
            }
        }
        __syncthreads();       // bar #3

        // ---- final: combine 2 M-quads, +b2, any-valid (1 polyline/tile) ----
        if (tid < 128) {
            const float v = fmaxf(red[tid], red[128 + tid]);
            const uint32_t av = flgs[0] | flgs[1];
            out[(size_t)tile * 128 + tid] = av ? v + __ldg(&b2g[tid]) : 0.0f;
        }

        buf ^= 1;
    }
}

extern "C" void kernel_launch(void* const* d_in, const int* in_sizes, int n_in,
                              void* d_out, int out_size)
{
    const float* poly = (const float*)d_in[0];
    const int*   mask = (const int*)  d_in[1];
    const float* W1   = (const float*)d_in[2];
    const float* b1   = (const float*)d_in[3];
    const float* W2   = (const float*)d_in[4];
    const float* b2   = (const float*)d_in[5];
    float* out = (float*)d_out;

    const int npoints = in_sizes[0] / 9;           // 1,048,576
    const int ntiles  = npoints / TILE_PTS;        // 16384

    prep_kernel<<<16, 256>>>(W1, W2);

    cudaFuncSetAttribute(poly_mma_kernel,
                         cudaFuncAttributeMaxDynamicSharedMemorySize, SM_BYTES);
    poly_mma_kernel<<<444, NT, SM_BYTES>>>(poly, mask, b1, b2, out, ntiles);
}